// round 6
// baseline (speedup 1.0000x reference)
#include <cuda_runtime.h>
#include <cstdint>
#include <math.h>

#define EPSV 1e-4f
#define NM   3249           // 57*57 floats per matrix
#define GM   4              // matrices per block
#define NQ   3249           // float4 quads per block
#define CHUNK 813           // quads per commit group (last one is 810)

// Scratch (allocation-free). Counter reset by last arriver -> graph-replay safe.
__device__ float g_a[128 * 64 * 3];
__device__ int   g_cnt[128];

// Shared layout (floats)
#define SM_X_OFF    0        // 12996: 4 staged matrices
#define SM_PQ_OFF   12996    // float2[57] = 114 floats
#define SM_W23_OFF  13110    // 40
#define SM_RED_OFF  13150    // 4 matrices * 15 warps * 3 = 180
#define SM_LAST_OFF 13330    // int flag
#define SM_FLOATS   13332
#define SM_BYTES    (SM_FLOATS * 4)

__device__ __forceinline__ void cp_async16(unsigned int saddr, const void* gptr) {
    asm volatile("cp.async.cg.shared.global [%0], [%1], 16;\n" :: "r"(saddr), "l"(gptr));
}
template <int N>
__device__ __forceinline__ void cp_wait() {
    asm volatile("cp.async.wait_group %0;\n" :: "n"(N) : "memory");
}

// Compute Pt X P for matrix m (staged in smem). 8 threads/row, shfl reductions.
__device__ __forceinline__ void compute_matrix(int m, const float* sm_x,
                                               const float2* sm_pq, float* sm_red,
                                               int tid) {
    const int lane = tid & 31, w = tid >> 5;
    const int row = tid >> 3, q = tid & 7;
    float y0 = 0.f, y1 = 0.f;
    if (tid < 456) {
        const float* xr = sm_x + m * NM + row * 57 + q * 7;
        #pragma unroll
        for (int j = 0; j < 7; j++) {
            float  vv = xr[j];
            float2 p  = sm_pq[q * 7 + j];
            y0 = fmaf(vv, p.x, y0);
            y1 = fmaf(vv, p.y, y1);
        }
        if (q == 7) {                         // 57th element
            float  vv = xr[7];
            float2 p  = sm_pq[56];
            y0 = fmaf(vv, p.x, y0);
            y1 = fmaf(vv, p.y, y1);
        }
    }
    // reduce y over the 8 lanes sharing a row
    y0 += __shfl_xor_sync(0xFFFFFFFFu, y0, 1);
    y1 += __shfl_xor_sync(0xFFFFFFFFu, y1, 1);
    y0 += __shfl_xor_sync(0xFFFFFFFFu, y0, 2);
    y1 += __shfl_xor_sync(0xFFFFFFFFu, y1, 2);
    y0 += __shfl_xor_sync(0xFFFFFFFFu, y0, 4);
    y1 += __shfl_xor_sync(0xFFFFFFFFu, y1, 4);

    float c00 = 0.f, c01 = 0.f, c11 = 0.f;
    if (tid < 456 && q == 0) {
        float2 pi = sm_pq[row];
        c00 = pi.x * y0; c01 = pi.x * y1; c11 = pi.y * y1;
    }
    // reduce c over the 4 rows in this warp
    c00 += __shfl_xor_sync(0xFFFFFFFFu, c00, 8);
    c01 += __shfl_xor_sync(0xFFFFFFFFu, c01, 8);
    c11 += __shfl_xor_sync(0xFFFFFFFFu, c11, 8);
    c00 += __shfl_xor_sync(0xFFFFFFFFu, c00, 16);
    c01 += __shfl_xor_sync(0xFFFFFFFFu, c01, 16);
    c11 += __shfl_xor_sync(0xFFFFFFFFu, c11, 16);
    if (lane == 0 && w < 15) {
        float* r = sm_red + (m * 15 + w) * 3;
        r[0] = c00; r[1] = c01; r[2] = c11;
    }
}

__global__ void __launch_bounds__(512, 4)
fused_kernel(const float* __restrict__ x,
             const float* __restrict__ W1,
             const float* __restrict__ W2,
             const float* __restrict__ W3,
             const float* __restrict__ lin_w,
             const float* __restrict__ lin_b,
             const float* __restrict__ alpha,
             float* __restrict__ out) {
    extern __shared__ float sm[];
    float*  sm_x   = sm + SM_X_OFF;
    float2* sm_pq  = (float2*)(sm + SM_PQ_OFF);
    float*  sm_w23 = sm + SM_W23_OFF;
    float*  sm_red = sm + SM_RED_OFF;
    int*    sm_last = (int*)(sm + SM_LAST_OFF);

    const int tid = threadIdx.x;
    const int blk = blockIdx.x;                 // 2048 blocks, 4 matrices each
    const float4* xq = (const float4*)(x + (size_t)blk * (GM * NM)); // 16B aligned

    unsigned int sx_base;
    asm("{ .reg .u64 t; cvta.to.shared.u64 t, %1; cvt.u32.u64 %0, t; }"
        : "=r"(sx_base) : "l"(sm_x));

    // --- Issue 4 commit groups; group prefix 0..m covers matrix m ---
    #pragma unroll
    for (int c = 0; c < 4; c++) {
        int base = c * CHUNK;
        int end  = (c == 3) ? NQ : base + CHUNK;
        int q1 = base + tid;
        if (q1 < end) cp_async16(sx_base + 16u * q1, &xq[q1]);
        int q2 = base + 512 + tid;
        if (q2 < end) cp_async16(sx_base + 16u * q2, &xq[q2]);
        asm volatile("cp.async.commit_group;\n" ::: "memory");
    }

    // --- P = W1@W2@W3 (hidden under the in-flight copies) ---
    if (tid < 40) {
        int j = tid >> 1, u = tid & 1;
        float s = 0.f;
        #pragma unroll
        for (int k = 0; k < 10; k++) s = fmaf(__ldg(W2 + j * 10 + k), __ldg(W3 + k * 2 + u), s);
        sm_w23[tid] = s;
    }
    __syncthreads();
    if (tid < 114) {
        int i = tid >> 1, u = tid & 1;
        float s = 0.f;
        #pragma unroll
        for (int j = 0; j < 20; j++) s = fmaf(__ldg(W1 + i * 20 + j), sm_w23[j * 2 + u], s);
        ((float*)&sm_pq[i])[u] = s;
    }
    __syncthreads();

    // --- Pipelined compute: matrix m overlaps loads of chunks m+1..3 ---
    cp_wait<3>(); __syncthreads();
    compute_matrix(0, sm_x, sm_pq, sm_red, tid);
    cp_wait<2>(); __syncthreads();
    compute_matrix(1, sm_x, sm_pq, sm_red, tid);
    cp_wait<1>(); __syncthreads();
    compute_matrix(2, sm_x, sm_pq, sm_red, tid);
    cp_wait<0>(); __syncthreads();
    compute_matrix(3, sm_x, sm_pq, sm_red, tid);
    __syncthreads();

    // --- Finalize: 12 threads sum 15 warp-partials each, publish ---
    if (tid < 12) {
        int m = tid / 3, comp = tid - 3 * m;
        const float* base = sm_red + (m * 15) * 3 + comp;
        float s = 0.f;
        #pragma unroll
        for (int w = 0; w < 15; w++) s += base[w * 3];
        g_a[(size_t)(GM * blk + m) * 3 + comp] = s;
    }
    __threadfence();
    __syncthreads();

    const int b = blk >> 4;                      // 16 blocks per b
    if (tid == 0) {
        int old = atomicAdd(&g_cnt[b], 1);
        *sm_last = (old == 15);
        if (old == 15) g_cnt[b] = 0;             // reset for graph replay
    }
    __syncthreads();
    if (!*sm_last) return;

    // --- Scan phase (only last-arriving block per b) ---
    __threadfence();                             // acquire
    float* a0 = sm_x;
    float* a1 = sm_x + 64;
    float* a2 = sm_x + 128;
    float* lw = sm_x + 192;                      // 51
    float* lb = sm_x + 243;                      // 17
    if (tid < 64) {
        const float* ab = g_a + ((size_t)b * 64 + tid) * 3;
        a0[tid] = ab[0]; a1[tid] = ab[1]; a2[tid] = ab[2];
    }
    if (tid < 51) lw[tid] = lin_w[tid];
    if (tid < 17) lb[tid] = lin_b[tid];
    __syncthreads();
    if (tid >= 64) return;

    const int t = tid;
    float s  = 1.f / (1.f + expf(-alpha[0]));
    float os = 1.f - s;

    float h00 = 0.f, h01 = 0.f, h11 = 0.f;
    for (int k = 0; k <= t; k++) {
        float mean = 0.5f * (h00 + h11);
        float diff = 0.5f * (h00 - h11);
        float rad  = sqrtf(diff * diff + h01 * h01);
        float r00, r01, r11;
        if (rad > 1e-20f) {
            float l1 = mean + rad, l2 = mean - rad;
            float m1 = fmaxf(l1, EPSV), m2 = fmaxf(l2, EPSV);
            float c1 = (m1 - m2) / (l1 - l2);
            float c0 = m1 - c1 * l1;
            r00 = c1 * h00 + c0;
            r01 = c1 * h01;
            r11 = c1 * h11 + c0;
        } else {
            if (mean >= EPSV) { r00 = h00; r01 = h01; r11 = h11; }
            else              { r00 = EPSV; r01 = 0.f; r11 = EPSV; }
        }
        h00 = fmaf(s, a0[k], os * r00);
        h01 = fmaf(s, a1[k], os * r01);
        h11 = fmaf(s, a2[k], os * r11);
    }

    float mean = 0.5f * (h00 + h11);
    float diff = 0.5f * (h00 - h11);
    float rad  = sqrtf(diff * diff + h01 * h01);
    float l1 = mean + rad, l2 = mean - rad;
    float d  = l1 - l2;
    float c1 = (d > 0.f) ? (log1pf(d / l2) / d) : (1.f / l1);
    float c0 = logf(l2) - c1 * l2;
    float v0 = c1 * h00 + c0;
    float v1 = c1 * h01;
    float v2 = c1 * h11 + c0;

    float* o = out + ((size_t)b * 64 + t) * 17;
    #pragma unroll
    for (int j = 0; j < 17; j++)
        o[j] = fmaf(lw[j * 3], v0, fmaf(lw[j * 3 + 1], v1, fmaf(lw[j * 3 + 2], v2, lb[j])));
}

// ---------------------------------------------------------------------------
extern "C" void kernel_launch(void* const* d_in, const int* in_sizes, int n_in,
                              void* d_out, int out_size) {
    const float* x     = (const float*)d_in[0];  // (128,64,57,57)
    const float* W1    = (const float*)d_in[1];  // (57,20)
    const float* W2    = (const float*)d_in[2];  // (20,10)
    const float* W3    = (const float*)d_in[3];  // (10,2)
    const float* lin_w = (const float*)d_in[4];  // (17,3)
    const float* lin_b = (const float*)d_in[5];  // (17,)
    const float* alpha = (const float*)d_in[6];  // (1,)
    float* out = (float*)d_out;                  // (128,64,17)

    cudaFuncSetAttribute(fused_kernel, cudaFuncAttributeMaxDynamicSharedMemorySize, SM_BYTES);
    fused_kernel<<<2048, 512, SM_BYTES>>>(x, W1, W2, W3, lin_w, lin_b, alpha, out);
}

// round 7
// speedup vs baseline: 1.4638x; 1.4638x over previous
#include <cuda_runtime.h>
#include <cstdint>
#include <math.h>

#define EPSV 1e-4f
#define NM   3249           // 57*57 floats per matrix
#define GM   4              // matrices per block
#define TILE_BYTES (GM * NM * 4)   // 51984, multiple of 16

// Scratch (allocation-free). Counter reset by last arriver -> graph-replay safe.
__device__ float g_a[128 * 64 * 3];
__device__ int   g_cnt[128];

// Shared layout (floats)
#define SM_X_OFF    0        // 12996: 4 staged matrices
#define SM_PQ_OFF   12996    // float2[57] = 114 floats
#define SM_W23_OFF  13110    // 40
#define SM_C_OFF    13150    // 228*3 per-row partials = 684
#define SM_LAST_OFF 13834    // int flag
#define SM_MBAR_OFF 13836    // 8B mbarrier (8-byte aligned: offset 13836*4 % 8 == 0)
#define SM_FLOATS   13840
#define SM_BYTES    (SM_FLOATS * 4)

__device__ __forceinline__ void mbar_init(unsigned int mbar, unsigned int cnt) {
    asm volatile("mbarrier.init.shared.b64 [%0], %1;" :: "r"(mbar), "r"(cnt) : "memory");
}
__device__ __forceinline__ void mbar_expect_tx(unsigned int mbar, unsigned int bytes) {
    asm volatile("mbarrier.arrive.expect_tx.shared.b64 _, [%0], %1;"
                 :: "r"(mbar), "r"(bytes) : "memory");
}
__device__ __forceinline__ void bulk_copy_g2s(unsigned int sdst, const void* gsrc,
                                              unsigned int bytes, unsigned int mbar) {
    asm volatile("cp.async.bulk.shared::cta.global.mbarrier::complete_tx::bytes "
                 "[%0], [%1], %2, [%3];"
                 :: "r"(sdst), "l"(gsrc), "r"(bytes), "r"(mbar) : "memory");
}
__device__ __forceinline__ void mbar_wait_parity(unsigned int mbar, unsigned int parity) {
    asm volatile(
        "{\n\t"
        ".reg .pred P1;\n\t"
        "WAIT_LOOP_%=:\n\t"
        "mbarrier.try_wait.parity.acquire.cta.shared::cta.b64 P1, [%0], %1, 0x989680;\n\t"
        "@P1 bra.uni WAIT_DONE_%=;\n\t"
        "bra.uni WAIT_LOOP_%=;\n\t"
        "WAIT_DONE_%=:\n\t"
        "}"
        :: "r"(mbar), "r"(parity) : "memory");
}

__global__ void __launch_bounds__(512, 4)
fused_kernel(const float* __restrict__ x,
             const float* __restrict__ W1,
             const float* __restrict__ W2,
             const float* __restrict__ W3,
             const float* __restrict__ lin_w,
             const float* __restrict__ lin_b,
             const float* __restrict__ alpha,
             float* __restrict__ out) {
    extern __shared__ float sm[];
    float*  sm_x   = sm + SM_X_OFF;
    float2* sm_pq  = (float2*)(sm + SM_PQ_OFF);
    float*  sm_w23 = sm + SM_W23_OFF;
    float*  sm_c   = sm + SM_C_OFF;
    int*    sm_last = (int*)(sm + SM_LAST_OFF);

    const int tid = threadIdx.x;
    const int blk = blockIdx.x;                 // 2048 blocks, 4 matrices each
    const float* xg = x + (size_t)blk * (GM * NM);

    unsigned int sbase;
    asm("{ .reg .u64 t; cvta.to.shared.u64 t, %1; cvt.u32.u64 %0, t; }"
        : "=r"(sbase) : "l"(sm));
    const unsigned int sx_addr   = sbase + SM_X_OFF * 4u;
    const unsigned int mbar_addr = sbase + SM_MBAR_OFF * 4u;

    // --- mbarrier init, then one TMA bulk copy for the whole 52KB tile ---
    if (tid == 0) mbar_init(mbar_addr, 1);
    __syncthreads();
    if (tid == 0) {
        mbar_expect_tx(mbar_addr, TILE_BYTES);
        bulk_copy_g2s(sx_addr, xg, TILE_BYTES, mbar_addr);
    }

    // --- P = W1@W2@W3 (hidden under the in-flight bulk copy) ---
    if (tid < 40) {
        int j = tid >> 1, u = tid & 1;
        float s = 0.f;
        #pragma unroll
        for (int k = 0; k < 10; k++) s = fmaf(__ldg(W2 + j * 10 + k), __ldg(W3 + k * 2 + u), s);
        sm_w23[tid] = s;
    }
    __syncthreads();
    if (tid < 114) {
        int i = tid >> 1, u = tid & 1;
        float s = 0.f;
        #pragma unroll
        for (int j = 0; j < 20; j++) s = fmaf(__ldg(W1 + i * 20 + j), sm_w23[j * 2 + u], s);
        ((float*)&sm_pq[i])[u] = s;
    }

    // --- Wait for the tile (HW-sleep try_wait), phase 0 ---
    mbar_wait_parity(mbar_addr, 0);
    __syncthreads();

    // --- Compute: thread t owns global row t (addr = t*57 + k), bank stride 25 ---
    if (tid < 228) {
        const float* xr = sm_x + tid * 57;
        float y0 = 0.f, y1 = 0.f;
        #pragma unroll
        for (int k = 0; k < 57; k++) {
            float  vv = xr[k];
            float2 p  = sm_pq[k];                // warp-uniform broadcast
            y0 = fmaf(vv, p.x, y0);
            y1 = fmaf(vv, p.y, y1);
        }
        int m = tid / 57;
        float2 pi = sm_pq[tid - 57 * m];
        sm_c[tid * 3 + 0] = pi.x * y0;
        sm_c[tid * 3 + 1] = pi.x * y1;
        sm_c[tid * 3 + 2] = pi.y * y1;
    }
    __syncthreads();

    // --- Finalize: 12 threads each sum 57 partials for (matrix m, component c) ---
    if (tid < 12) {
        int m = tid / 3;
        int comp = tid - 3 * m;
        const float* base = sm_c + (m * 57) * 3 + comp;
        float s = 0.f;
        #pragma unroll
        for (int r = 0; r < 57; r++) s += base[r * 3];
        g_a[(size_t)(GM * blk + m) * 3 + comp] = s;
    }
    __threadfence();
    __syncthreads();

    const int b = blk >> 4;                      // 16 blocks per b
    if (tid == 0) {
        int old = atomicAdd(&g_cnt[b], 1);
        *sm_last = (old == 15);
        if (old == 15) g_cnt[b] = 0;             // reset for graph replay
    }
    __syncthreads();
    if (!*sm_last) return;

    // --- Scan phase (only last-arriving block per b) ---
    __threadfence();                             // acquire
    float* a0 = sm_x;                            // reuse staged region
    float* a1 = sm_x + 64;
    float* a2 = sm_x + 128;
    float* lw = sm_x + 192;                      // 51
    float* lb = sm_x + 243;                      // 17
    if (tid < 64) {
        const float* ab = g_a + ((size_t)b * 64 + tid) * 3;
        a0[tid] = ab[0]; a1[tid] = ab[1]; a2[tid] = ab[2];
    }
    if (tid < 51) lw[tid] = lin_w[tid];
    if (tid < 17) lb[tid] = lin_b[tid];
    __syncthreads();
    if (tid >= 64) return;

    const int t = tid;
    float s  = 1.f / (1.f + expf(-alpha[0]));
    float os = 1.f - s;

    float h00 = 0.f, h01 = 0.f, h11 = 0.f;
    for (int k = 0; k <= t; k++) {
        float mean = 0.5f * (h00 + h11);
        float diff = 0.5f * (h00 - h11);
        float rad  = sqrtf(diff * diff + h01 * h01);
        float r00, r01, r11;
        if (rad > 1e-20f) {
            float l1 = mean + rad, l2 = mean - rad;
            float m1 = fmaxf(l1, EPSV), m2 = fmaxf(l2, EPSV);
            float c1 = (m1 - m2) / (l1 - l2);
            float c0 = m1 - c1 * l1;
            r00 = c1 * h00 + c0;
            r01 = c1 * h01;
            r11 = c1 * h11 + c0;
        } else {
            if (mean >= EPSV) { r00 = h00; r01 = h01; r11 = h11; }
            else              { r00 = EPSV; r01 = 0.f; r11 = EPSV; }
        }
        h00 = fmaf(s, a0[k], os * r00);
        h01 = fmaf(s, a1[k], os * r01);
        h11 = fmaf(s, a2[k], os * r11);
    }

    float mean = 0.5f * (h00 + h11);
    float diff = 0.5f * (h00 - h11);
    float rad  = sqrtf(diff * diff + h01 * h01);
    float l1 = mean + rad, l2 = mean - rad;
    float d  = l1 - l2;
    float c1 = (d > 0.f) ? (log1pf(d / l2) / d) : (1.f / l1);
    float c0 = logf(l2) - c1 * l2;
    float v0 = c1 * h00 + c0;
    float v1 = c1 * h01;
    float v2 = c1 * h11 + c0;

    float* o = out + ((size_t)b * 64 + t) * 17;
    #pragma unroll
    for (int j = 0; j < 17; j++)
        o[j] = fmaf(lw[j * 3], v0, fmaf(lw[j * 3 + 1], v1, fmaf(lw[j * 3 + 2], v2, lb[j])));
}

// ---------------------------------------------------------------------------
extern "C" void kernel_launch(void* const* d_in, const int* in_sizes, int n_in,
                              void* d_out, int out_size) {
    const float* x     = (const float*)d_in[0];  // (128,64,57,57)
    const float* W1    = (const float*)d_in[1];  // (57,20)
    const float* W2    = (const float*)d_in[2];  // (20,10)
    const float* W3    = (const float*)d_in[3];  // (10,2)
    const float* lin_w = (const float*)d_in[4];  // (17,3)
    const float* lin_b = (const float*)d_in[5];  // (17,)
    const float* alpha = (const float*)d_in[6];  // (1,)
    float* out = (float*)d_out;                  // (128,64,17)

    cudaFuncSetAttribute(fused_kernel, cudaFuncAttributeMaxDynamicSharedMemorySize, SM_BYTES);
    fused_kernel<<<2048, 512, SM_BYTES>>>(x, W1, W2, W3, lin_w, lin_b, alpha, out);
}